// round 8
// baseline (speedup 1.0000x reference)
#include <cuda_runtime.h>
#include <cuda_bf16.h>

// Problem constants
#define CH   64
#define HW   1296
#define NTOT (CH * HW)   // 82944
#define LOG2E 1.4426950408889634f

#define SEGS 6            // j-segments per attn block
#define OPB  32           // outputs per attn block (= warp width)
#define J4   (HW / 4)     // 324 float4 per channel row
#define JSEG (J4 / SEGS)  // 54 float4 per segment

#define TPX  16           // pixels per proj tile (81 tiles exactly)

typedef unsigned long long u64;

// Scratch (device globals; float4 forces 16B alignment)
__device__ float4 g_q4 [NTOT / 4];
__device__ float4 g_k4 [NTOT / 4];   // k * log2e (SoA)
__device__ float4 g_v4 [NTOT / 4];   // v         (SoA)
__device__ float4 g_yp4[NTOT / 4];

__device__ __forceinline__ float ex2f(float x) {
    float r;
    asm("ex2.approx.f32 %0, %1;" : "=f"(r) : "f"(x));
    return r;
}
// FMA-pipe exp2: round via magic constant, deg-4 Horner, exponent insert.
// |arg| < ~45 here; rel err ~4e-5.
__device__ __forceinline__ float ex2p(float a) {
    float t = a + 12582912.0f;            // 2^23 + 2^22: n in mantissa
    float f = a - (t - 12582912.0f);      // f in [-0.5, 0.5]
    float p = 0.0096181291f;
    p = fmaf(p, f, 0.0555041087f);
    p = fmaf(p, f, 0.2402265069f);
    p = fmaf(p, f, 0.6931471806f);
    p = fmaf(p, f, 1.0f);
    return __int_as_float(__float_as_int(p) + (__float_as_int(t) << 23));
}
__device__ __forceinline__ u64 pack2(float lo, float hi) {
    u64 r; asm("mov.b64 %0, {%1, %2};" : "=l"(r) : "f"(lo), "f"(hi)); return r;
}
__device__ __forceinline__ void unpack2(float& lo, float& hi, u64 v) {
    asm("mov.b64 {%0, %1}, %2;" : "=f"(lo), "=f"(hi) : "l"(v));
}
__device__ __forceinline__ u64 mul2(u64 a, u64 b) {
    u64 r; asm("mul.rn.f32x2 %0, %1, %2;" : "=l"(r) : "l"(a), "l"(b)); return r;
}
__device__ __forceinline__ void adda2(u64& d, u64 a) {
    asm("add.rn.f32x2 %0, %1, %0;" : "+l"(d) : "l"(a));
}
__device__ __forceinline__ void fma2(u64& d, u64 a, u64 b) {
    asm("fma.rn.f32x2 %0, %1, %2, %0;" : "+l"(d) : "l"(a), "l"(b));
}

// ---------------------------------------------------------------------------
// Kernel A: smem-tiled 1x1-conv projections. Each source pixel is read from
// gmem ONCE per (pair, o-half) instead of 64x -> kills the L2-BW floor.
// Grid: (81 px-tiles, 4): blockIdx.y = pair*2 + ohalf.
//   pair 0: q & k from x ; pair 1: v & yp from y.  ohalf: o in [0,32) or [32,64).
// Block 128 thr = 4 warps x 4-px quads; lane = local o (32 distinct -> the
// 65-padded W rows are bank-conflict-free); x tile read as broadcast LDS.128.
// ---------------------------------------------------------------------------
__global__ void proj_kernel(const float* __restrict__ x,
                            const float* __restrict__ y,
                            const float* __restrict__ Wq, const float* __restrict__ bq,
                            const float* __restrict__ Wk, const float* __restrict__ bk,
                            const float* __restrict__ Wv, const float* __restrict__ bv,
                            const float* __restrict__ Wp) {
    __shared__ float w1s[32 * 65];
    __shared__ float w2s[32 * 65];
    __shared__ float xt[64 * TPX];

    int pair  = blockIdx.y >> 1;
    int ohalf = blockIdx.y & 1;
    int i0    = blockIdx.x * TPX;
    int t     = threadIdx.x;

    const float* src = (pair == 0) ? x  : y;
    const float* W1  = (pair == 0) ? Wq : Wv;
    const float* W2  = (pair == 0) ? Wk : Wp;

    // Stage 32 W-rows of each matrix (coalesced gmem, padded smem)
    for (int idx = t; idx < 32 * 64; idx += 128) {
        int ol = idx >> 6, c = idx & 63;
        w1s[ol * 65 + c] = __ldg(&W1[ohalf * 2048 + idx]);
        w2s[ol * 65 + c] = __ldg(&W2[ohalf * 2048 + idx]);
    }
    // Stage source tile xt[c][px]
    for (int idx = t; idx < 64 * TPX; idx += 128) {
        int c = idx >> 4, px = idx & 15;
        xt[c * TPX + px] = __ldg(&src[c * HW + i0 + px]);
    }
    __syncthreads();

    int lane = t & 31;                 // local o
    int pxq  = (t >> 5) * 4;           // warp's pixel quad
    int o    = ohalf * 32 + lane;

    float b1 = (pair == 0) ? __ldg(&bq[o]) : __ldg(&bv[o]);
    float b2 = (pair == 0) ? __ldg(&bk[o]) : 0.0f;
    float4 a1 = make_float4(b1, b1, b1, b1);
    float4 a2 = make_float4(b2, b2, b2, b2);

    #pragma unroll 8
    for (int c = 0; c < 64; c++) {
        float w1 = w1s[lane * 65 + c];
        float w2 = w2s[lane * 65 + c];
        float4 xv = *reinterpret_cast<const float4*>(&xt[c * TPX + pxq]);
        a1.x = fmaf(w1, xv.x, a1.x); a1.y = fmaf(w1, xv.y, a1.y);
        a1.z = fmaf(w1, xv.z, a1.z); a1.w = fmaf(w1, xv.w, a1.w);
        a2.x = fmaf(w2, xv.x, a2.x); a2.y = fmaf(w2, xv.y, a2.y);
        a2.z = fmaf(w2, xv.z, a2.z); a2.w = fmaf(w2, xv.w, a2.w);
    }

    int idx4 = (o * HW + i0 + pxq) >> 2;
    if (pair == 0) {
        g_q4[idx4] = a1;
        g_k4[idx4] = make_float4(a2.x * LOG2E, a2.y * LOG2E,
                                 a2.z * LOG2E, a2.w * LOG2E);
    } else {
        g_v4[idx4]  = a1;
        g_yp4[idx4] = a2;
    }
}

// ---------------------------------------------------------------------------
// Kernel B: attention + gated residual.
// One block = one channel x 32 outputs x 6 j-segments (192 threads).
// k/v staged in smem (warp-uniform LDS.128 broadcast). MUFU is saturated
// (R6 vs R7 invariance) -> offload 1 exp in 8 to the FMA-pipe polynomial
// ex2p, using the measured spare issue/fma capacity.
// Shiftless softmax: |q.k| << 88 by construction; ratio is scale-invariant.
// ---------------------------------------------------------------------------
__global__ void attn_kernel(const float* __restrict__ gamma,
                            float* __restrict__ out) {
    __shared__ ulonglong2 ks2[J4];    // 4 packed k*log2e per entry
    __shared__ ulonglong2 vs2[J4];
    __shared__ float2 part[SEGS * OPB];

    int c  = blockIdx.y;
    int i0 = blockIdx.x * OPB;
    int t  = threadIdx.x;          // 0..191
    int il = t & 31;               // lane -> output
    int seg = t >> 5;              // warp -> j-segment (uniform per warp)

    const ulonglong2* gk = reinterpret_cast<const ulonglong2*>(&g_k4[c * J4]);
    const ulonglong2* gv = reinterpret_cast<const ulonglong2*>(&g_v4[c * J4]);
    for (int idx = t; idx < J4; idx += SEGS * OPB) {
        ks2[idx] = gk[idx];
        vs2[idx] = gv[idx];
    }
    __syncthreads();

    int i = i0 + il;
    bool valid = (i < HW);
    float s = reinterpret_cast<const float*>(g_q4)[c * HW + (valid ? i : 0)];
    u64 s2 = pack2(s, s);

    int j0 = seg * JSEG;
    u64 d01 = 0, d23 = 0, n01 = 0, n23 = 0;   // bit pattern (0.f, 0.f)
    #pragma unroll 3
    for (int j = j0; j < j0 + JSEG; j += 2) {  // 8 exps per iteration
        ulonglong2 ka = ks2[j];
        ulonglong2 kb = ks2[j + 1];
        ulonglong2 va = vs2[j];
        ulonglong2 vb = vs2[j + 1];
        u64 a01 = mul2(ka.x, s2);
        u64 a23 = mul2(ka.y, s2);
        u64 a45 = mul2(kb.x, s2);
        u64 a67 = mul2(kb.y, s2);
        float f0, f1, f2, f3, f4, f5, f6, f7;
        unpack2(f0, f1, a01);
        unpack2(f2, f3, a23);
        unpack2(f4, f5, a45);
        unpack2(f6, f7, a67);
        u64 t01 = pack2(ex2f(f0), ex2f(f1));
        u64 t23 = pack2(ex2f(f2), ex2f(f3));
        u64 t45 = pack2(ex2f(f4), ex2f(f5));
        u64 t67 = pack2(ex2f(f6), ex2p(f7));   // 1-in-8 via FMA pipe
        adda2(d01, t01); fma2(n01, t01, va.x);
        adda2(d23, t23); fma2(n23, t23, va.y);
        adda2(d01, t45); fma2(n01, t45, vb.x);
        adda2(d23, t67); fma2(n23, t67, vb.y);
    }

    float a, b, e, f;
    unpack2(a, b, d01); unpack2(e, f, d23);
    float dsum = (a + b) + (e + f);
    unpack2(a, b, n01); unpack2(e, f, n23);
    float nsum = (a + b) + (e + f);

    part[t] = make_float2(dsum, nsum);
    __syncthreads();

    if (seg == 0 && valid) {
        float dd = 0.0f, nn = 0.0f;
        #pragma unroll
        for (int ss = 0; ss < SEGS; ss++) {
            float2 p = part[ss * OPB + il];
            dd += p.x; nn += p.y;
        }
        float gm = __ldg(&gamma[0]);
        float yp = reinterpret_cast<const float*>(g_yp4)[c * HW + i];
        out[c * HW + i] = (gm * (nn / dd) + yp) / (1.0f + gm);
    }
}

// ---------------------------------------------------------------------------
extern "C" void kernel_launch(void* const* d_in, const int* in_sizes, int n_in,
                              void* d_out, int out_size) {
    const float* x     = (const float*)d_in[0];
    const float* y     = (const float*)d_in[1];
    const float* Wq    = (const float*)d_in[2];
    const float* bq    = (const float*)d_in[3];
    const float* Wk    = (const float*)d_in[4];
    const float* bk    = (const float*)d_in[5];
    const float* Wv    = (const float*)d_in[6];
    const float* bv    = (const float*)d_in[7];
    const float* Wp    = (const float*)d_in[8];
    const float* gamma = (const float*)d_in[9];
    float* out = (float*)d_out;

    dim3 pgrid(HW / TPX, 4);               // (81, 4)
    proj_kernel<<<pgrid, 128>>>(x, y, Wq, bq, Wk, bk, Wv, bv, Wp);

    dim3 agrid((HW + OPB - 1) / OPB, CH);  // (41, 64)
    attn_kernel<<<agrid, SEGS * OPB>>>(gamma, out);
}